// round 9
// baseline (speedup 1.0000x reference)
#include <cuda_runtime.h>
#include <cuda_fp16.h>
#include <cstdint>

#define N_NODES 16384
#define N_EDGES 32768
#define D 128
#define EDGE_DIM 10
#define EH 32
#define NCOLS (EH * D + D + D)   // 4096 (L) + 128 (l2 bias) + 128 (root) = 4352
#define KS 256                   // fp16 2-term split: A=[hi|lo], B=[hi;hi]
#define BM 128
#define BN 256
#define STAGE3 (BM * 128 + BN * 128)   // 48 KB per stage (A 16K + B 32K)

// ---------------- scratch (static device globals; no allocation) ----------------
__device__ __half g_Y[N_NODES * NCOLS];    // 142 MB (fp16 Y)
__device__ __half g_A3[N_NODES * KS];
__device__ __half g_B31[NCOLS * KS];
__device__ __half g_B32[NCOLS * KS];
__device__ float g_h1[N_EDGES * EH];
__device__ float g_h2[N_EDGES * EH];
__device__ float g_acc[N_NODES * D];       // zero-init; every combine restores zero
__device__ float g_cnt[N_NODES];
__device__ int   g_idx[2 * N_EDGES];
__device__ int   g_is64;
// edge sort-by-src
__device__ int g_srcCount[N_NODES];
__device__ int g_srcOff[N_NODES];
__device__ int g_rank[N_EDGES];
__device__ int g_perm[N_EDGES];

__device__ __forceinline__ uint32_t smem_u32(const void* p) {
    uint32_t a;
    asm("{ .reg .u64 t; cvta.to.shared.u64 t, %1; cvt.u32.u64 %0, t; }" : "=r"(a) : "l"(p));
    return a;
}
#define CP_ASYNC16(saddr, gptr) \
    asm volatile("cp.async.cg.shared.global [%0], [%1], 16;" :: "r"(saddr), "l"(gptr))
#define CP_COMMIT() asm volatile("cp.async.commit_group;" ::: "memory")
#define CP_WAITG(n) asm volatile("cp.async.wait_group %0;" :: "n"(n) : "memory")

// ---------------- edge_index dtype detection + normalization ----------------
__global__ void detect_idx(const long long* __restrict__ ei) {
    if (threadIdx.x == 0 && blockIdx.x == 0) {
        int ok = 1;
        for (int i = 0; i < 128; i++) {
            long long v = ei[i];
            if (v < 0 || v >= N_NODES) { ok = 0; break; }
        }
        g_is64 = ok;
    }
}
__global__ void convert_idx(const void* __restrict__ ei) {
    int i = blockIdx.x * blockDim.x + threadIdx.x;
    if (i >= 2 * N_EDGES) return;
    long long v = g_is64 ? ((const long long*)ei)[i] : (long long)((const int*)ei)[i];
    int iv = (int)v;
    iv = iv < 0 ? 0 : (iv >= N_NODES ? N_NODES - 1 : iv);
    g_idx[i] = iv;
}

// ---------------- edge sorting by src + one-time dst counts ----------------
__global__ void zero_setup() {
    int i = blockIdx.x * blockDim.x + threadIdx.x;
    if (i < N_NODES) { g_srcCount[i] = 0; g_cnt[i] = 0.f; }
}
__global__ void count_edges() {
    int e = blockIdx.x * blockDim.x + threadIdx.x;
    if (e >= N_EDGES) return;
    g_rank[e] = atomicAdd(&g_srcCount[g_idx[e]], 1);
    atomicAdd(&g_cnt[g_idx[N_EDGES + e]], 1.0f);
}
__global__ void scan_counts() {          // 1 block, 1024 threads, 16 elems each
    __shared__ int part[1024];
    int t = threadIdx.x;
    int base = t * 16;
    int local[16];
    int s = 0;
#pragma unroll
    for (int i = 0; i < 16; i++) { local[i] = s; s += g_srcCount[base + i]; }
    part[t] = s;
    __syncthreads();
    for (int off = 1; off < 1024; off <<= 1) {
        int v = (t >= off) ? part[t - off] : 0;
        __syncthreads();
        part[t] += v;
        __syncthreads();
    }
    int pre = (t == 0) ? 0 : part[t - 1];
#pragma unroll
    for (int i = 0; i < 16; i++) g_srcOff[base + i] = pre + local[i];
}
__global__ void place_edges() {
    int e = blockIdx.x * blockDim.x + threadIdx.x;
    if (e >= N_EDGES) return;
    g_perm[g_srcOff[g_idx[e]] + g_rank[e]] = e;
}

// ---------------- h = relu(edge_attr @ l1w + l1b), both weight sets ----------------
__global__ void build_h2(const float* __restrict__ ea,
                         const float* __restrict__ wA, const float* __restrict__ bA,
                         const float* __restrict__ wB, const float* __restrict__ bB,
                         float* __restrict__ hA, float* __restrict__ hB) {
    int idx = blockIdx.x * blockDim.x + threadIdx.x;
    if (idx >= N_EDGES * EH) return;
    int e = idx >> 5, j = idx & 31;
    const float* ear = ea + e * EDGE_DIM;
    float sA = bA[j], sB = bB[j];
#pragma unroll
    for (int d = 0; d < EDGE_DIM; d++) {
        float v = ear[d];
        sA = fmaf(v, wA[d * EH + j], sA);
        sB = fmaf(v, wB[d * EH + j], sB);
    }
    hA[idx] = fmaxf(sA, 0.f);
    hB[idx] = fmaxf(sB, 0.f);
}

// ---------------- fp16 2-term split of A (layer-1 input only) ----------------
__global__ void convA(const float* __restrict__ X, __half* __restrict__ A3) {
    int idx = blockIdx.x * blockDim.x + threadIdx.x;
    if (idx >= N_NODES * D) return;
    int r = idx >> 7, c = idx & 127;
    float v = X[idx];
    __half hi = __float2half_rn(v);
    __half lo = __float2half_rn(v - __half2float(hi));
    __half* row = A3 + (size_t)r * KS;
    row[c] = hi; row[c + 128] = lo;
}

// ---------------- B'[n, k]: permuted l2w | l2 bias | root, fp16 (duplicated) ----------------
__global__ void buildB(const float* __restrict__ l2w, const float* __restrict__ b_l2,
                       const float* __restrict__ root, __half* __restrict__ B3) {
    int idx = blockIdx.x * blockDim.x + threadIdx.x;   // n*128 + k
    if (idx >= NCOLS * D) return;
    int n = idx >> 7, k = idx & 127;
    float v;
    if (n < EH * D)            v = l2w[(n >> 7) * (D * D) + k * D + (n & 127)];
    else if (n < EH * D + D)   v = b_l2[k * D + (n - EH * D)];
    else                       v = root[k * D + (n - EH * D - D)];
    __half hi = __float2half_rn(v);
    __half* row = B3 + (size_t)n * KS;
    row[k] = hi; row[k + 128] = hi;
}

// ---------------- HMMA GEMM: 3-stage cp.async, CTA 128x256, warp tile 64x64 ----------------
// Y[16384 x 4352] = A'[.,256] @ B'^T. 8 warps: warp_m in {0,1}, warp_n in {0..3}.
__global__ void __launch_bounds__(256, 1) gemm_mma(const __half* __restrict__ A,
                                                   const __half* __restrict__ B,
                                                   __half* __restrict__ C) {
    extern __shared__ __align__(1024) char smem[];
    const int tid = threadIdx.x, lane = tid & 31, wid = tid >> 5;
    const int warp_m = wid & 1, warp_n = wid >> 1;       // 2 x 4, each 64x64
    const int rowBase = blockIdx.y * BM;
    const int colBase = blockIdx.x * BN;
    const uint32_t smemU = smem_u32(smem);
    const char* Ab = (const char*)A;
    const char* Bb = (const char*)B;

    float acc[4][8][4];
#pragma unroll
    for (int i = 0; i < 4; i++)
#pragma unroll
        for (int j = 0; j < 8; j++)
#pragma unroll
            for (int r = 0; r < 4; r++) acc[i][j][r] = 0.f;

    const int ldr = tid >> 3;            // 0..31
    const int ldc = tid & 7;             // 16B unit within 128B row

    auto load_stage = [&](int st, int ch) {
        uint32_t sa = smemU + st * STAGE3;
        uint32_t sb = sa + BM * 128;
#pragma unroll
        for (int i = 0; i < 4; i++) {    // A: 128 rows
            int r = ldr + i * 32;
            uint32_t soff = (uint32_t)(r * 128 + ((ldc * 16) ^ ((r & 7) * 16)));
            CP_ASYNC16(sa + soff, Ab + (size_t)(rowBase + r) * (KS * 2) + ch * 128 + ldc * 16);
        }
#pragma unroll
        for (int i = 0; i < 8; i++) {    // B: 256 rows
            int r = ldr + i * 32;
            uint32_t soff = (uint32_t)(r * 128 + ((ldc * 16) ^ ((r & 7) * 16)));
            CP_ASYNC16(sb + soff, Bb + (size_t)(colBase + r) * (KS * 2) + ch * 128 + ldc * 16);
        }
        CP_COMMIT();
    };

    load_stage(0, 0);
    load_stage(1, 1);

    for (int ch = 0; ch < 4; ch++) {               // K = 256 = 4 chunks of 64
        if (ch < 2) { CP_WAITG(1); } else { CP_WAITG(0); }
        __syncthreads();
        if (ch + 2 < 4) load_stage((ch + 2) % 3, ch + 2);

        const uint32_t aB = smemU + (ch % 3) * STAGE3;
        const uint32_t bB = aB + BM * 128;
#pragma unroll
        for (int s = 0; s < 4; s++) {              // 4 x k16 within chunk
            uint32_t af[4][4], bf[8][2];
#pragma unroll
            for (int i = 0; i < 4; i++) {
                int row = warp_m * 64 + i * 16 + (lane & 15);
                int kb = s * 32 + ((lane >> 4) << 4);
                uint32_t addr = aB + row * 128 + (kb ^ ((row & 7) * 16));
                asm volatile("ldmatrix.sync.aligned.m8n8.x4.shared.b16 {%0,%1,%2,%3}, [%4];"
                             : "=r"(af[i][0]), "=r"(af[i][1]), "=r"(af[i][2]), "=r"(af[i][3])
                             : "r"(addr));
            }
#pragma unroll
            for (int j = 0; j < 8; j++) {
                int nrow = warp_n * 64 + j * 8 + (lane & 7);
                int kb = s * 32 + (((lane >> 3) & 1) << 4);
                uint32_t addr = bB + nrow * 128 + (kb ^ ((nrow & 7) * 16));
                asm volatile("ldmatrix.sync.aligned.m8n8.x2.shared.b16 {%0,%1}, [%2];"
                             : "=r"(bf[j][0]), "=r"(bf[j][1]) : "r"(addr));
            }
#pragma unroll
            for (int i = 0; i < 4; i++)
#pragma unroll
                for (int j = 0; j < 8; j++)
                    asm volatile(
                        "mma.sync.aligned.m16n8k16.row.col.f32.f16.f16.f32 "
                        "{%0,%1,%2,%3}, {%4,%5,%6,%7}, {%8,%9}, {%0,%1,%2,%3};"
                        : "+f"(acc[i][j][0]), "+f"(acc[i][j][1]),
                          "+f"(acc[i][j][2]), "+f"(acc[i][j][3])
                        : "r"(af[i][0]), "r"(af[i][1]), "r"(af[i][2]), "r"(af[i][3]),
                          "r"(bf[j][0]), "r"(bf[j][1]));
        }
        __syncthreads();
    }

    // Epilogue: fp16 stores (half2), warp region 64x64
#pragma unroll
    for (int i = 0; i < 4; i++) {
        int r0 = rowBase + warp_m * 64 + i * 16 + (lane >> 2);
#pragma unroll
        for (int j = 0; j < 8; j++) {
            int col = colBase + warp_n * 64 + j * 8 + (lane & 3) * 2;
            *(__half2*)&C[(size_t)r0 * NCOLS + col] =
                __floats2half2_rn(acc[i][j][0], acc[i][j][1]);
            *(__half2*)&C[(size_t)(r0 + 8) * NCOLS + col] =
                __floats2half2_rn(acc[i][j][2], acc[i][j][3]);
        }
    }
}

// ---------------- edge message (src-sorted, fp16 gather) + scatter-add ----------------
__global__ void __launch_bounds__(256) edge_msg(const float* __restrict__ h,
                                                const __half* __restrict__ Y) {
    const int q = threadIdx.x >> 6;           // edge-within-block 0..3
    const int slot = blockIdx.x * 4 + q;
    const int o2 = threadIdx.x & 63;          // half2 column index
    __shared__ float sh[4][EH];
    __shared__ int se[4];
    if (o2 == 0) se[q] = g_perm[slot];
    __syncthreads();
    const int eo = se[q];
    if (o2 < EH) sh[q][o2] = h[eo * EH + o2];
    __syncthreads();
    const int src = g_idx[eo];
    const int dst = g_idx[N_EDGES + eo];
    const __half2* y2 = (const __half2*)(Y + (size_t)src * NCOLS);
    float2 b2 = __half22float2(y2[(EH * D) / 2 + o2]);    // l2-bias columns
    float mx = b2.x, my = b2.y;
#pragma unroll
    for (int k = 0; k < EH; k++) {
        float2 v = __half22float2(y2[k * 64 + o2]);
        float hk = sh[q][k];
        mx = fmaf(hk, v.x, mx);
        my = fmaf(hk, v.y, my);
    }
    atomicAdd(&g_acc[dst * D + 2 * o2], mx);
    atomicAdd(&g_acc[dst * D + 2 * o2 + 1], my);
}

// ---------------- combine: out = Yroot + acc/max(cnt,1) + bias; resets acc to 0 ----------------
__global__ void combine(const __half* __restrict__ Y, const float* __restrict__ bias,
                        float* __restrict__ outf, __half* __restrict__ A3,
                        int do_relu) {
    int idx = blockIdx.x * blockDim.x + threadIdx.x;
    if (idx >= N_NODES * D) return;
    int n = idx >> 7, o = idx & 127;
    float v = __half2float(Y[(size_t)n * NCOLS + EH * D + D + o])
            + g_acc[idx] / fmaxf(g_cnt[n], 1.f) + bias[o];
    g_acc[idx] = 0.f;                         // reset for next layer / next replay
    if (do_relu) v = fmaxf(v, 0.f);
    if (outf) outf[idx] = v;
    if (A3) {
        __half hi = __float2half_rn(v);
        __half lo = __float2half_rn(v - __half2float(hi));
        __half* row = A3 + (size_t)n * KS;
        row[o] = hi; row[o + 128] = lo;
    }
}

// ---------------- launcher ----------------
extern "C" void kernel_launch(void* const* d_in, const int* in_sizes, int n_in,
                              void* d_out, int out_size) {
    const float* x       = (const float*)d_in[0];
    const void*  ei      = d_in[1];
    const float* ea      = (const float*)d_in[2];
    const float* w1_l1   = (const float*)d_in[3];
    const float* b1_l1   = (const float*)d_in[4];
    const float* w1_l2   = (const float*)d_in[5];
    const float* b1_l2   = (const float*)d_in[6];
    const float* w1_root = (const float*)d_in[7];
    const float* b1      = (const float*)d_in[8];
    const float* w2_l1   = (const float*)d_in[9];
    const float* b2_l1   = (const float*)d_in[10];
    const float* w2_l2   = (const float*)d_in[11];
    const float* b2_l2   = (const float*)d_in[12];
    const float* w2_root = (const float*)d_in[13];
    const float* b2      = (const float*)d_in[14];
    float*       out     = (float*)d_out;

    __half *Y, *A3, *B31, *B32;
    float *h1, *h2;
    cudaGetSymbolAddress((void**)&Y,   g_Y);
    cudaGetSymbolAddress((void**)&A3,  g_A3);
    cudaGetSymbolAddress((void**)&B31, g_B31);
    cudaGetSymbolAddress((void**)&B32, g_B32);
    cudaGetSymbolAddress((void**)&h1,  g_h1);
    cudaGetSymbolAddress((void**)&h2,  g_h2);

    const int SMEM_GEMM = 3 * STAGE3;                   // 144 KB
    cudaFuncSetAttribute(gemm_mma, cudaFuncAttributeMaxDynamicSharedMemorySize, SMEM_GEMM);

    // ---- setup (indices, sort, edge MLP, weights) ----
    detect_idx<<<1, 32>>>((const long long*)ei);
    convert_idx<<<(2 * N_EDGES + 255) / 256, 256>>>(ei);
    zero_setup<<<(N_NODES + 255) / 256, 256>>>();
    count_edges<<<(N_EDGES + 255) / 256, 256>>>();
    scan_counts<<<1, 1024>>>();
    place_edges<<<(N_EDGES + 255) / 256, 256>>>();
    build_h2<<<(N_EDGES * EH + 255) / 256, 256>>>(ea, w1_l1, b1_l1, w2_l1, b2_l1, h1, h2);
    buildB<<<(NCOLS * D + 255) / 256, 256>>>(w1_l2, b1_l2, w1_root, B31);
    buildB<<<(NCOLS * D + 255) / 256, 256>>>(w2_l2, b2_l2, w2_root, B32);

    dim3 gGemm(NCOLS / BN, N_NODES / BM);               // (17, 128)
    const int zgrid = (N_NODES * D + 255) / 256;
    const int egrid = N_EDGES / 4;

    // ---- layer 1 ----
    convA<<<zgrid, 256>>>(x, A3);
    gemm_mma<<<gGemm, 256, SMEM_GEMM>>>(A3, B31, Y);
    edge_msg<<<egrid, 256>>>(h1, Y);
    combine<<<zgrid, 256>>>(Y, b1, nullptr, A3, 1);
    // ---- layer 2 ----
    gemm_mma<<<gGemm, 256, SMEM_GEMM>>>(A3, B32, Y);
    edge_msg<<<egrid, 256>>>(h2, Y);
    combine<<<zgrid, 256>>>(Y, b2, nullptr, A3, 1);
    // ---- layer 3 ----
    gemm_mma<<<gGemm, 256, SMEM_GEMM>>>(A3, B32, Y);
    edge_msg<<<egrid, 256>>>(h2, Y);
    combine<<<zgrid, 256>>>(Y, b2, out, nullptr, 0);
}

// round 10
// speedup vs baseline: 1.0177x; 1.0177x over previous
#include <cuda_runtime.h>
#include <cuda_fp16.h>
#include <cstdint>

#define N_NODES 16384
#define N_EDGES 32768
#define D 128
#define EDGE_DIM 10
#define EH 32
#define NCOLS (EH * D + D + D)   // 4096 (L) + 128 (l2 bias) + 128 (root) = 4352
#define KS 256                   // fp16 2-term split: A=[hi|lo], B=[hi;hi]
#define BM 128
#define BN 128
#define STAGE_BYTES (BM * 128 + BN * 128)   // 32 KB per stage

// ---------------- scratch (static device globals; no allocation) ----------------
__device__ __half g_Y[N_NODES * NCOLS];    // 142 MB (fp16 Y)
__device__ __half g_A3[N_NODES * KS];
__device__ __half g_B31[NCOLS * KS];
__device__ __half g_B32[NCOLS * KS];
__device__ float g_h1[N_EDGES * EH];
__device__ float g_h2[N_EDGES * EH];
__device__ float g_acc[N_NODES * D];       // zero-init; every combine restores zero
__device__ float g_cnt[N_NODES];
__device__ int   g_idx[2 * N_EDGES];
__device__ int   g_is64;
// edge sort-by-src (CSR)
__device__ int g_srcCount[N_NODES];
__device__ int g_srcOff[N_NODES];
__device__ int g_rank[N_EDGES];
__device__ int g_perm[N_EDGES];

__device__ __forceinline__ uint32_t smem_u32(const void* p) {
    uint32_t a;
    asm("{ .reg .u64 t; cvta.to.shared.u64 t, %1; cvt.u32.u64 %0, t; }" : "=r"(a) : "l"(p));
    return a;
}
#define CP_ASYNC16(saddr, gptr) \
    asm volatile("cp.async.cg.shared.global [%0], [%1], 16;" :: "r"(saddr), "l"(gptr))
#define CP_COMMIT() asm volatile("cp.async.commit_group;" ::: "memory")
#define CP_WAIT0()  asm volatile("cp.async.wait_group 0;" ::: "memory")

// ---------------- edge_index dtype detection + normalization ----------------
__global__ void detect_idx(const long long* __restrict__ ei) {
    if (threadIdx.x == 0 && blockIdx.x == 0) {
        int ok = 1;
        for (int i = 0; i < 128; i++) {
            long long v = ei[i];
            if (v < 0 || v >= N_NODES) { ok = 0; break; }
        }
        g_is64 = ok;
    }
}
__global__ void convert_idx(const void* __restrict__ ei) {
    int i = blockIdx.x * blockDim.x + threadIdx.x;
    if (i >= 2 * N_EDGES) return;
    long long v = g_is64 ? ((const long long*)ei)[i] : (long long)((const int*)ei)[i];
    int iv = (int)v;
    iv = iv < 0 ? 0 : (iv >= N_NODES ? N_NODES - 1 : iv);
    g_idx[i] = iv;
}

// ---------------- edge sorting by src + one-time dst counts ----------------
__global__ void zero_setup() {
    int i = blockIdx.x * blockDim.x + threadIdx.x;
    if (i < N_NODES) { g_srcCount[i] = 0; g_cnt[i] = 0.f; }
}
__global__ void count_edges() {
    int e = blockIdx.x * blockDim.x + threadIdx.x;
    if (e >= N_EDGES) return;
    g_rank[e] = atomicAdd(&g_srcCount[g_idx[e]], 1);
    atomicAdd(&g_cnt[g_idx[N_EDGES + e]], 1.0f);
}
__global__ void scan_counts() {          // 1 block, 1024 threads, 16 elems each
    __shared__ int part[1024];
    int t = threadIdx.x;
    int base = t * 16;
    int local[16];
    int s = 0;
#pragma unroll
    for (int i = 0; i < 16; i++) { local[i] = s; s += g_srcCount[base + i]; }
    part[t] = s;
    __syncthreads();
    for (int off = 1; off < 1024; off <<= 1) {
        int v = (t >= off) ? part[t - off] : 0;
        __syncthreads();
        part[t] += v;
        __syncthreads();
    }
    int pre = (t == 0) ? 0 : part[t - 1];
#pragma unroll
    for (int i = 0; i < 16; i++) g_srcOff[base + i] = pre + local[i];
}
__global__ void place_edges() {
    int e = blockIdx.x * blockDim.x + threadIdx.x;
    if (e >= N_EDGES) return;
    g_perm[g_srcOff[g_idx[e]] + g_rank[e]] = e;
}

// ---------------- h = relu(edge_attr @ l1w + l1b), both weight sets ----------------
__global__ void build_h2(const float* __restrict__ ea,
                         const float* __restrict__ wA, const float* __restrict__ bA,
                         const float* __restrict__ wB, const float* __restrict__ bB,
                         float* __restrict__ hA, float* __restrict__ hB) {
    int idx = blockIdx.x * blockDim.x + threadIdx.x;
    if (idx >= N_EDGES * EH) return;
    int e = idx >> 5, j = idx & 31;
    const float* ear = ea + e * EDGE_DIM;
    float sA = bA[j], sB = bB[j];
#pragma unroll
    for (int d = 0; d < EDGE_DIM; d++) {
        float v = ear[d];
        sA = fmaf(v, wA[d * EH + j], sA);
        sB = fmaf(v, wB[d * EH + j], sB);
    }
    hA[idx] = fmaxf(sA, 0.f);
    hB[idx] = fmaxf(sB, 0.f);
}

// ---------------- fp16 2-term split of A (layer-1 input only) ----------------
__global__ void convA(const float* __restrict__ X, __half* __restrict__ A3) {
    int idx = blockIdx.x * blockDim.x + threadIdx.x;
    if (idx >= N_NODES * D) return;
    int r = idx >> 7, c = idx & 127;
    float v = X[idx];
    __half hi = __float2half_rn(v);
    __half lo = __float2half_rn(v - __half2float(hi));
    __half* row = A3 + (size_t)r * KS;
    row[c] = hi; row[c + 128] = lo;
}

// ---------------- B'[n, k]: permuted l2w | l2 bias | root, fp16 (duplicated) ----------------
__global__ void buildB(const float* __restrict__ l2w, const float* __restrict__ b_l2,
                       const float* __restrict__ root, __half* __restrict__ B3) {
    int idx = blockIdx.x * blockDim.x + threadIdx.x;   // n*128 + k
    if (idx >= NCOLS * D) return;
    int n = idx >> 7, k = idx & 127;
    float v;
    if (n < EH * D)            v = l2w[(n >> 7) * (D * D) + k * D + (n & 127)];
    else if (n < EH * D + D)   v = b_l2[k * D + (n - EH * D)];
    else                       v = root[k * D + (n - EH * D - D)];
    __half hi = __float2half_rn(v);
    __half* row = B3 + (size_t)n * KS;
    row[k] = hi; row[k + 128] = hi;
}

// ---------------- HMMA GEMM (R8 config: 2-stage cp.async, CTA 128x128, warp 64x32) ----------------
__global__ void __launch_bounds__(256) gemm_mma(const __half* __restrict__ A,
                                                const __half* __restrict__ B,
                                                __half* __restrict__ C) {
    extern __shared__ __align__(1024) char smem[];
    const int tid = threadIdx.x, lane = tid & 31, wid = tid >> 5;
    const int warp_m = wid & 1, warp_n = wid >> 1;       // 2 x 4
    const int rowBase = blockIdx.y * BM;
    const int colBase = blockIdx.x * BN;
    const uint32_t smemU = smem_u32(smem);
    const char* Ab = (const char*)A;
    const char* Bb = (const char*)B;

    float acc[4][4][4];
#pragma unroll
    for (int i = 0; i < 4; i++)
#pragma unroll
        for (int j = 0; j < 4; j++)
#pragma unroll
            for (int r = 0; r < 4; r++) acc[i][j][r] = 0.f;

    const int ldr = tid >> 3;
    const int ldc = tid & 7;

    auto load_stage = [&](int st, int ch) {
        uint32_t sa = smemU + st * STAGE_BYTES;
        uint32_t sb = sa + BM * 128;
#pragma unroll
        for (int i = 0; i < 4; i++) {
            int r = ldr + i * 32;
            uint32_t soff = (uint32_t)(r * 128 + ((ldc * 16) ^ ((r & 7) * 16)));
            CP_ASYNC16(sa + soff, Ab + (size_t)(rowBase + r) * (KS * 2) + ch * 128 + ldc * 16);
            CP_ASYNC16(sb + soff, Bb + (size_t)(colBase + r) * (KS * 2) + ch * 128 + ldc * 16);
        }
        CP_COMMIT();
    };

    load_stage(0, 0);

    for (int ch = 0; ch < 4; ch++) {               // K = 256 = 4 chunks of 64
        CP_WAIT0();
        __syncthreads();
        if (ch < 3) load_stage((ch + 1) & 1, ch + 1);

        const uint32_t aB = smemU + (ch & 1) * STAGE_BYTES;
        const uint32_t bB = aB + BM * 128;
#pragma unroll
        for (int s = 0; s < 4; s++) {
            uint32_t af[4][4], bf[4][2];
#pragma unroll
            for (int i = 0; i < 4; i++) {
                int row = warp_m * 64 + i * 16 + (lane & 15);
                int kb = s * 32 + ((lane >> 4) << 4);
                uint32_t addr = aB + row * 128 + (kb ^ ((row & 7) * 16));
                asm volatile("ldmatrix.sync.aligned.m8n8.x4.shared.b16 {%0,%1,%2,%3}, [%4];"
                             : "=r"(af[i][0]), "=r"(af[i][1]), "=r"(af[i][2]), "=r"(af[i][3])
                             : "r"(addr));
            }
#pragma unroll
            for (int j = 0; j < 4; j++) {
                int nrow = warp_n * 32 + j * 8 + (lane & 7);
                int kb = s * 32 + (((lane >> 3) & 1) << 4);
                uint32_t addr = bB + nrow * 128 + (kb ^ ((nrow & 7) * 16));
                asm volatile("ldmatrix.sync.aligned.m8n8.x2.shared.b16 {%0,%1}, [%2];"
                             : "=r"(bf[j][0]), "=r"(bf[j][1]) : "r"(addr));
            }
#pragma unroll
            for (int i = 0; i < 4; i++)
#pragma unroll
                for (int j = 0; j < 4; j++)
                    asm volatile(
                        "mma.sync.aligned.m16n8k16.row.col.f32.f16.f16.f32 "
                        "{%0,%1,%2,%3}, {%4,%5,%6,%7}, {%8,%9}, {%0,%1,%2,%3};"
                        : "+f"(acc[i][j][0]), "+f"(acc[i][j][1]),
                          "+f"(acc[i][j][2]), "+f"(acc[i][j][3])
                        : "r"(af[i][0]), "r"(af[i][1]), "r"(af[i][2]), "r"(af[i][3]),
                          "r"(bf[j][0]), "r"(bf[j][1]));
        }
        __syncthreads();
    }

    // Epilogue: fp16 stores (half2)
#pragma unroll
    for (int i = 0; i < 4; i++) {
        int r0 = rowBase + warp_m * 64 + i * 16 + (lane >> 2);
#pragma unroll
        for (int j = 0; j < 4; j++) {
            int col = colBase + warp_n * 32 + j * 8 + (lane & 3) * 2;
            *(__half2*)&C[(size_t)r0 * NCOLS + col] =
                __floats2half2_rn(acc[i][j][0], acc[i][j][1]);
            *(__half2*)&C[(size_t)(r0 + 8) * NCOLS + col] =
                __floats2half2_rn(acc[i][j][2], acc[i][j][3]);
        }
    }
}

// ---------------- CSR edge message: one src node per 64-thread block ----------------
// Y[src] slice loaded into registers ONCE, reused for all edges of that src.
__global__ void __launch_bounds__(64) edge_msg(const float* __restrict__ h,
                                               const __half* __restrict__ Y) {
    const int src = blockIdx.x;
    const int cnt = g_srcCount[src];
    if (cnt == 0) return;
    const int o2 = threadIdx.x;               // half2 column 0..63
    const __half2* y2 = (const __half2*)(Y + (size_t)src * NCOLS);
    float2 yb = __half22float2(y2[(EH * D) / 2 + o2]);   // l2-bias columns
    float2 yk[EH];
#pragma unroll
    for (int k = 0; k < EH; k++) yk[k] = __half22float2(y2[k * 64 + o2]);

    const int off = g_srcOff[src];
    __shared__ float sh[EH];
    __shared__ int sdst;
    for (int i = 0; i < cnt; i++) {
        const int eo = g_perm[off + i];
        if (o2 < EH) sh[o2] = h[eo * EH + o2];
        if (o2 == 32) sdst = g_idx[N_EDGES + eo];
        __syncthreads();
        float mx = yb.x, my = yb.y;
#pragma unroll
        for (int k = 0; k < EH; k++) {
            mx = fmaf(sh[k], yk[k].x, mx);
            my = fmaf(sh[k], yk[k].y, my);
        }
        const int dst = sdst;
        __syncthreads();                      // protect sh/sdst before next iter
        atomicAdd(&g_acc[dst * D + 2 * o2], mx);
        atomicAdd(&g_acc[dst * D + 2 * o2 + 1], my);
    }
}

// ---------------- combine: out = Yroot + acc/max(cnt,1) + bias; resets acc to 0 ----------------
__global__ void combine(const __half* __restrict__ Y, const float* __restrict__ bias,
                        float* __restrict__ outf, __half* __restrict__ A3,
                        int do_relu) {
    int idx = blockIdx.x * blockDim.x + threadIdx.x;
    if (idx >= N_NODES * D) return;
    int n = idx >> 7, o = idx & 127;
    float v = __half2float(Y[(size_t)n * NCOLS + EH * D + D + o])
            + g_acc[idx] / fmaxf(g_cnt[n], 1.f) + bias[o];
    g_acc[idx] = 0.f;                         // reset for next layer / next replay
    if (do_relu) v = fmaxf(v, 0.f);
    if (outf) outf[idx] = v;
    if (A3) {
        __half hi = __float2half_rn(v);
        __half lo = __float2half_rn(v - __half2float(hi));
        __half* row = A3 + (size_t)n * KS;
        row[o] = hi; row[o + 128] = lo;
    }
}

// ---------------- launcher ----------------
extern "C" void kernel_launch(void* const* d_in, const int* in_sizes, int n_in,
                              void* d_out, int out_size) {
    const float* x       = (const float*)d_in[0];
    const void*  ei      = d_in[1];
    const float* ea      = (const float*)d_in[2];
    const float* w1_l1   = (const float*)d_in[3];
    const float* b1_l1   = (const float*)d_in[4];
    const float* w1_l2   = (const float*)d_in[5];
    const float* b1_l2   = (const float*)d_in[6];
    const float* w1_root = (const float*)d_in[7];
    const float* b1      = (const float*)d_in[8];
    const float* w2_l1   = (const float*)d_in[9];
    const float* b2_l1   = (const float*)d_in[10];
    const float* w2_l2   = (const float*)d_in[11];
    const float* b2_l2   = (const float*)d_in[12];
    const float* w2_root = (const float*)d_in[13];
    const float* b2      = (const float*)d_in[14];
    float*       out     = (float*)d_out;

    __half *Y, *A3, *B31, *B32;
    float *h1, *h2;
    cudaGetSymbolAddress((void**)&Y,   g_Y);
    cudaGetSymbolAddress((void**)&A3,  g_A3);
    cudaGetSymbolAddress((void**)&B31, g_B31);
    cudaGetSymbolAddress((void**)&B32, g_B32);
    cudaGetSymbolAddress((void**)&h1,  g_h1);
    cudaGetSymbolAddress((void**)&h2,  g_h2);

    const int SMEM_GEMM = 2 * STAGE_BYTES;              // 64 KB
    cudaFuncSetAttribute(gemm_mma, cudaFuncAttributeMaxDynamicSharedMemorySize, SMEM_GEMM);

    // ---- setup (indices, sort, edge MLP, weights) ----
    detect_idx<<<1, 32>>>((const long long*)ei);
    convert_idx<<<(2 * N_EDGES + 255) / 256, 256>>>(ei);
    zero_setup<<<(N_NODES + 255) / 256, 256>>>();
    count_edges<<<(N_EDGES + 255) / 256, 256>>>();
    scan_counts<<<1, 1024>>>();
    place_edges<<<(N_EDGES + 255) / 256, 256>>>();
    build_h2<<<(N_EDGES * EH + 255) / 256, 256>>>(ea, w1_l1, b1_l1, w2_l1, b2_l1, h1, h2);
    buildB<<<(NCOLS * D + 255) / 256, 256>>>(w1_l2, b1_l2, w1_root, B31);
    buildB<<<(NCOLS * D + 255) / 256, 256>>>(w2_l2, b2_l2, w2_root, B32);

    dim3 gGemm(NCOLS / BN, N_NODES / BM);               // (34, 128)
    const int zgrid = (N_NODES * D + 255) / 256;

    // ---- layer 1 ----
    convA<<<zgrid, 256>>>(x, A3);
    gemm_mma<<<gGemm, 256, SMEM_GEMM>>>(A3, B31, Y);
    edge_msg<<<N_NODES, 64>>>(h1, Y);
    combine<<<zgrid, 256>>>(Y, b1, nullptr, A3, 1);
    // ---- layer 2 ----
    gemm_mma<<<gGemm, 256, SMEM_GEMM>>>(A3, B32, Y);
    edge_msg<<<N_NODES, 64>>>(h2, Y);
    combine<<<zgrid, 256>>>(Y, b2, nullptr, A3, 1);
    // ---- layer 3 ----
    gemm_mma<<<gGemm, 256, SMEM_GEMM>>>(A3, B32, Y);
    edge_msg<<<N_NODES, 64>>>(h2, Y);
    combine<<<zgrid, 256>>>(Y, b2, out, nullptr, 0);
}

// round 11
// speedup vs baseline: 1.0701x; 1.0515x over previous
#include <cuda_runtime.h>
#include <cuda_fp16.h>
#include <cstdint>

#define N_NODES 16384
#define N_EDGES 32768
#define D 128
#define EDGE_DIM 10
#define EH 32
#define NCOLS (EH * D + D + D)   // 4096 (L) + 128 (l2 bias) + 128 (root) = 4352
#define KS 256                   // fp16 2-term split: A=[hi|lo], B=[hi;hi]
#define BM 128
#define BN 128
#define STAGE_BYTES (BM * 128 + BN * 128)   // 32 KB per stage

// ---------------- scratch (static device globals; no allocation) ----------------
__device__ __half g_Y[N_NODES * NCOLS];    // 142 MB (fp16 Y)
__device__ __half g_A3[N_NODES * KS];
__device__ __half g_B31[NCOLS * KS];
__device__ __half g_B32[NCOLS * KS];
__device__ float g_h1[N_EDGES * EH];
__device__ float g_h2[N_EDGES * EH];
__device__ float g_acc[N_NODES * D];       // zero-init; every combine restores zero
__device__ float g_cnt[N_NODES];
__device__ int   g_idx[2 * N_EDGES];
__device__ int   g_is64;
// edge sort-by-src
__device__ int g_srcCount[N_NODES];
__device__ int g_srcOff[N_NODES];
__device__ int g_rank[N_EDGES];
__device__ int g_perm[N_EDGES];

__device__ __forceinline__ uint32_t smem_u32(const void* p) {
    uint32_t a;
    asm("{ .reg .u64 t; cvta.to.shared.u64 t, %1; cvt.u32.u64 %0, t; }" : "=r"(a) : "l"(p));
    return a;
}
#define CP_ASYNC16(saddr, gptr) \
    asm volatile("cp.async.cg.shared.global [%0], [%1], 16;" :: "r"(saddr), "l"(gptr))
#define CP_COMMIT() asm volatile("cp.async.commit_group;" ::: "memory")
#define CP_WAITG(n) asm volatile("cp.async.wait_group %0;" :: "n"(n) : "memory")

// ---------------- edge_index dtype detection ----------------
__global__ void detect_zero(const long long* __restrict__ ei) {
    int i = blockIdx.x * blockDim.x + threadIdx.x;
    if (i < N_NODES) { g_srcCount[i] = 0; g_cnt[i] = 0.f; }
    if (i == 0) {
        int ok = 1;
        for (int k = 0; k < 128; k++) {
            long long v = ei[k];
            if (v < 0 || v >= N_NODES) { ok = 0; break; }
        }
        g_is64 = ok;
    }
}

// ---------------- convert indices + count (fused) ----------------
__global__ void conv_count(const void* __restrict__ ei) {
    int e = blockIdx.x * blockDim.x + threadIdx.x;
    if (e >= N_EDGES) return;
    long long vs, vd;
    if (g_is64) {
        vs = ((const long long*)ei)[e];
        vd = ((const long long*)ei)[N_EDGES + e];
    } else {
        vs = ((const int*)ei)[e];
        vd = ((const int*)ei)[N_EDGES + e];
    }
    int s = (int)vs, d = (int)vd;
    s = s < 0 ? 0 : (s >= N_NODES ? N_NODES - 1 : s);
    d = d < 0 ? 0 : (d >= N_NODES ? N_NODES - 1 : d);
    g_idx[e] = s;
    g_idx[N_EDGES + e] = d;
    g_rank[e] = atomicAdd(&g_srcCount[s], 1);
    atomicAdd(&g_cnt[d], 1.0f);
}

__global__ void scan_counts() {          // 1 block, 1024 threads, 16 elems each
    __shared__ int part[1024];
    int t = threadIdx.x;
    int base = t * 16;
    int local[16];
    int s = 0;
#pragma unroll
    for (int i = 0; i < 16; i++) { local[i] = s; s += g_srcCount[base + i]; }
    part[t] = s;
    __syncthreads();
    for (int off = 1; off < 1024; off <<= 1) {
        int v = (t >= off) ? part[t - off] : 0;
        __syncthreads();
        part[t] += v;
        __syncthreads();
    }
    int pre = (t == 0) ? 0 : part[t - 1];
#pragma unroll
    for (int i = 0; i < 16; i++) g_srcOff[base + i] = pre + local[i];
}

// ---------------- h = relu(edge_attr @ l1w + l1b) both sets + place_edges (fused) ----------------
__global__ void build_h2(const float* __restrict__ ea,
                         const float* __restrict__ wA, const float* __restrict__ bA,
                         const float* __restrict__ wB, const float* __restrict__ bB,
                         float* __restrict__ hA, float* __restrict__ hB) {
    int idx = blockIdx.x * blockDim.x + threadIdx.x;
    if (idx >= N_EDGES * EH) return;
    int e = idx >> 5, j = idx & 31;
    if (j == 0) g_perm[g_srcOff[g_idx[e]] + g_rank[e]] = e;   // place edge in sorted order
    const float* ear = ea + e * EDGE_DIM;
    float sA = bA[j], sB = bB[j];
#pragma unroll
    for (int d = 0; d < EDGE_DIM; d++) {
        float v = ear[d];
        sA = fmaf(v, wA[d * EH + j], sA);
        sB = fmaf(v, wB[d * EH + j], sB);
    }
    hA[idx] = fmaxf(sA, 0.f);
    hB[idx] = fmaxf(sB, 0.f);
}

// ---------------- fp16 2-term split of A (layer-1 input only) ----------------
__global__ void convA(const float* __restrict__ X, __half* __restrict__ A3) {
    int idx = blockIdx.x * blockDim.x + threadIdx.x;
    if (idx >= N_NODES * D) return;
    int r = idx >> 7, c = idx & 127;
    float v = X[idx];
    __half hi = __float2half_rn(v);
    __half lo = __float2half_rn(v - __half2float(hi));
    __half* row = A3 + (size_t)r * KS;
    row[c] = hi; row[c + 128] = lo;
}

// ---------------- both B' matrices in one kernel ----------------
__global__ void buildB2(const float* __restrict__ l2wA, const float* __restrict__ bA,
                        const float* __restrict__ rootA,
                        const float* __restrict__ l2wB, const float* __restrict__ bB,
                        const float* __restrict__ rootB,
                        __half* __restrict__ B3A, __half* __restrict__ B3B) {
    int idx = blockIdx.x * blockDim.x + threadIdx.x;   // n*128 + k
    if (idx >= NCOLS * D) return;
    int n = idx >> 7, k = idx & 127;
    float vA, vB;
    if (n < EH * D) {
        int pos = (n >> 7) * (D * D) + k * D + (n & 127);
        vA = l2wA[pos]; vB = l2wB[pos];
    } else if (n < EH * D + D) {
        int pos = k * D + (n - EH * D);
        vA = bA[pos]; vB = bB[pos];
    } else {
        int pos = k * D + (n - EH * D - D);
        vA = rootA[pos]; vB = rootB[pos];
    }
    __half hiA = __float2half_rn(vA);
    __half hiB = __float2half_rn(vB);
    __half* rowA = B3A + (size_t)n * KS;
    __half* rowB = B3B + (size_t)n * KS;
    rowA[k] = hiA; rowA[k + 128] = hiA;
    rowB[k] = hiB; rowB[k + 128] = hiB;
}

// ---------------- HMMA GEMM: 3-stage cp.async, CTA 128x128, warp 64x32 ----------------
__global__ void __launch_bounds__(256) gemm_mma(const __half* __restrict__ A,
                                                const __half* __restrict__ B,
                                                __half* __restrict__ C) {
    extern __shared__ __align__(1024) char smem[];
    const int tid = threadIdx.x, lane = tid & 31, wid = tid >> 5;
    const int warp_m = wid & 1, warp_n = wid >> 1;       // 2 x 4
    const int rowBase = blockIdx.y * BM;
    const int colBase = blockIdx.x * BN;
    const uint32_t smemU = smem_u32(smem);
    const char* Ab = (const char*)A;
    const char* Bb = (const char*)B;

    float acc[4][4][4];
#pragma unroll
    for (int i = 0; i < 4; i++)
#pragma unroll
        for (int j = 0; j < 4; j++)
#pragma unroll
            for (int r = 0; r < 4; r++) acc[i][j][r] = 0.f;

    const int ldr = tid >> 3;
    const int ldc = tid & 7;

    auto load_stage = [&](int st, int ch) {
        uint32_t sa = smemU + st * STAGE_BYTES;
        uint32_t sb = sa + BM * 128;
#pragma unroll
        for (int i = 0; i < 4; i++) {
            int r = ldr + i * 32;
            uint32_t soff = (uint32_t)(r * 128 + ((ldc * 16) ^ ((r & 7) * 16)));
            CP_ASYNC16(sa + soff, Ab + (size_t)(rowBase + r) * (KS * 2) + ch * 128 + ldc * 16);
            CP_ASYNC16(sb + soff, Bb + (size_t)(colBase + r) * (KS * 2) + ch * 128 + ldc * 16);
        }
        CP_COMMIT();
    };

    load_stage(0, 0);
    load_stage(1, 1);

    for (int ch = 0; ch < 4; ch++) {               // K = 256 = 4 chunks of 64
        if (ch < 3) { CP_WAITG(1); } else { CP_WAITG(0); }
        __syncthreads();
        if (ch + 2 < 4) load_stage((ch + 2) % 3, ch + 2);

        const uint32_t aB = smemU + (ch % 3) * STAGE_BYTES;
        const uint32_t bB = aB + BM * 128;
#pragma unroll
        for (int s = 0; s < 4; s++) {
            uint32_t af[4][4], bf[4][2];
#pragma unroll
            for (int i = 0; i < 4; i++) {
                int row = warp_m * 64 + i * 16 + (lane & 15);
                int kb = s * 32 + ((lane >> 4) << 4);
                uint32_t addr = aB + row * 128 + (kb ^ ((row & 7) * 16));
                asm volatile("ldmatrix.sync.aligned.m8n8.x4.shared.b16 {%0,%1,%2,%3}, [%4];"
                             : "=r"(af[i][0]), "=r"(af[i][1]), "=r"(af[i][2]), "=r"(af[i][3])
                             : "r"(addr));
            }
            // B fragments: one x4 ldmatrix covers two adjacent n8 tiles (j, j+1)
#pragma unroll
            for (int jp = 0; jp < 2; jp++) {
                int nrow = warp_n * 32 + (jp * 2 + (lane >> 4)) * 8 + (lane & 7);
                int kb = s * 32 + (((lane >> 3) & 1) << 4);
                uint32_t addr = bB + nrow * 128 + (kb ^ ((nrow & 7) * 16));
                asm volatile("ldmatrix.sync.aligned.m8n8.x4.shared.b16 {%0,%1,%2,%3}, [%4];"
                             : "=r"(bf[jp * 2][0]), "=r"(bf[jp * 2][1]),
                               "=r"(bf[jp * 2 + 1][0]), "=r"(bf[jp * 2 + 1][1])
                             : "r"(addr));
            }
#pragma unroll
            for (int i = 0; i < 4; i++)
#pragma unroll
                for (int j = 0; j < 4; j++)
                    asm volatile(
                        "mma.sync.aligned.m16n8k16.row.col.f32.f16.f16.f32 "
                        "{%0,%1,%2,%3}, {%4,%5,%6,%7}, {%8,%9}, {%0,%1,%2,%3};"
                        : "+f"(acc[i][j][0]), "+f"(acc[i][j][1]),
                          "+f"(acc[i][j][2]), "+f"(acc[i][j][3])
                        : "r"(af[i][0]), "r"(af[i][1]), "r"(af[i][2]), "r"(af[i][3]),
                          "r"(bf[j][0]), "r"(bf[j][1]));
        }
        __syncthreads();
    }

    // Epilogue: fp16 stores (half2)
#pragma unroll
    for (int i = 0; i < 4; i++) {
        int r0 = rowBase + warp_m * 64 + i * 16 + (lane >> 2);
#pragma unroll
        for (int j = 0; j < 4; j++) {
            int col = colBase + warp_n * 32 + j * 8 + (lane & 3) * 2;
            *(__half2*)&C[(size_t)r0 * NCOLS + col] =
                __floats2half2_rn(acc[i][j][0], acc[i][j][1]);
            *(__half2*)&C[(size_t)(r0 + 8) * NCOLS + col] =
                __floats2half2_rn(acc[i][j][2], acc[i][j][3]);
        }
    }
}

// ---------------- edge message (src-sorted flat, fp16 gather) + scatter-add ----------------
__global__ void __launch_bounds__(256) edge_msg(const float* __restrict__ h,
                                                const __half* __restrict__ Y) {
    const int q = threadIdx.x >> 6;           // edge-within-block 0..3
    const int slot = blockIdx.x * 4 + q;
    const int o2 = threadIdx.x & 63;          // half2 column index
    __shared__ float sh[4][EH];
    __shared__ int se[4];
    if (o2 == 0) se[q] = g_perm[slot];
    __syncthreads();
    const int eo = se[q];
    if (o2 < EH) sh[q][o2] = h[eo * EH + o2];
    __syncthreads();
    const int src = g_idx[eo];
    const int dst = g_idx[N_EDGES + eo];
    const __half2* y2 = (const __half2*)(Y + (size_t)src * NCOLS);
    float2 b2 = __half22float2(y2[(EH * D) / 2 + o2]);    // l2-bias columns
    float mx = b2.x, my = b2.y;
#pragma unroll
    for (int k = 0; k < EH; k++) {
        float2 v = __half22float2(y2[k * 64 + o2]);
        float hk = sh[q][k];
        mx = fmaf(hk, v.x, mx);
        my = fmaf(hk, v.y, my);
    }
    atomicAdd(&g_acc[dst * D + 2 * o2], mx);
    atomicAdd(&g_acc[dst * D + 2 * o2 + 1], my);
}

// ---------------- combine: out = Yroot + acc/max(cnt,1) + bias; resets acc to 0 ----------------
__global__ void combine(const __half* __restrict__ Y, const float* __restrict__ bias,
                        float* __restrict__ outf, __half* __restrict__ A3,
                        int do_relu) {
    int idx = blockIdx.x * blockDim.x + threadIdx.x;
    if (idx >= N_NODES * D) return;
    int n = idx >> 7, o = idx & 127;
    float v = __half2float(Y[(size_t)n * NCOLS + EH * D + D + o])
            + g_acc[idx] / fmaxf(g_cnt[n], 1.f) + bias[o];
    g_acc[idx] = 0.f;                         // reset for next layer / next replay
    if (do_relu) v = fmaxf(v, 0.f);
    if (outf) outf[idx] = v;
    if (A3) {
        __half hi = __float2half_rn(v);
        __half lo = __float2half_rn(v - __half2float(hi));
        __half* row = A3 + (size_t)n * KS;
        row[o] = hi; row[o + 128] = lo;
    }
}

// ---------------- launcher ----------------
extern "C" void kernel_launch(void* const* d_in, const int* in_sizes, int n_in,
                              void* d_out, int out_size) {
    const float* x       = (const float*)d_in[0];
    const void*  ei      = d_in[1];
    const float* ea      = (const float*)d_in[2];
    const float* w1_l1   = (const float*)d_in[3];
    const float* b1_l1   = (const float*)d_in[4];
    const float* w1_l2   = (const float*)d_in[5];
    const float* b1_l2   = (const float*)d_in[6];
    const float* w1_root = (const float*)d_in[7];
    const float* b1      = (const float*)d_in[8];
    const float* w2_l1   = (const float*)d_in[9];
    const float* b2_l1   = (const float*)d_in[10];
    const float* w2_l2   = (const float*)d_in[11];
    const float* b2_l2   = (const float*)d_in[12];
    const float* w2_root = (const float*)d_in[13];
    const float* b2      = (const float*)d_in[14];
    float*       out     = (float*)d_out;

    __half *Y, *A3, *B31, *B32;
    float *h1, *h2;
    cudaGetSymbolAddress((void**)&Y,   g_Y);
    cudaGetSymbolAddress((void**)&A3,  g_A3);
    cudaGetSymbolAddress((void**)&B31, g_B31);
    cudaGetSymbolAddress((void**)&B32, g_B32);
    cudaGetSymbolAddress((void**)&h1,  g_h1);
    cudaGetSymbolAddress((void**)&h2,  g_h2);

    const int SMEM_GEMM = 3 * STAGE_BYTES;              // 96 KB
    cudaFuncSetAttribute(gemm_mma, cudaFuncAttributeMaxDynamicSharedMemorySize, SMEM_GEMM);

    // ---- setup (indices+counts, scan, sort+edge MLP, weights) ----
    detect_zero<<<(N_NODES + 255) / 256, 256>>>((const long long*)ei);
    conv_count<<<(N_EDGES + 255) / 256, 256>>>(ei);
    scan_counts<<<1, 1024>>>();
    build_h2<<<(N_EDGES * EH + 255) / 256, 256>>>(ea, w1_l1, b1_l1, w2_l1, b2_l1, h1, h2);
    buildB2<<<(NCOLS * D + 255) / 256, 256>>>(w1_l2, b1_l2, w1_root,
                                              w2_l2, b2_l2, w2_root, B31, B32);

    dim3 gGemm(NCOLS / BN, N_NODES / BM);               // (34, 128)
    const int zgrid = (N_NODES * D + 255) / 256;
    const int egrid = N_EDGES / 4;

    // ---- layer 1 ----
    convA<<<zgrid, 256>>>(x, A3);
    gemm_mma<<<gGemm, 256, SMEM_GEMM>>>(A3, B31, Y);
    edge_msg<<<egrid, 256>>>(h1, Y);
    combine<<<zgrid, 256>>>(Y, b1, nullptr, A3, 1);
    // ---- layer 2 ----
    gemm_mma<<<gGemm, 256, SMEM_GEMM>>>(A3, B32, Y);
    edge_msg<<<egrid, 256>>>(h2, Y);
    combine<<<zgrid, 256>>>(Y, b2, nullptr, A3, 1);
    // ---- layer 3 ----
    gemm_mma<<<gGemm, 256, SMEM_GEMM>>>(A3, B32, Y);
    edge_msg<<<egrid, 256>>>(h2, Y);
    combine<<<zgrid, 256>>>(Y, b2, out, nullptr, 0);
}

// round 12
// speedup vs baseline: 1.4705x; 1.3742x over previous
#include <cuda_runtime.h>
#include <cuda_fp16.h>
#include <cstdint>

#define N_NODES 16384
#define N_EDGES 32768
#define D 128
#define EDGE_DIM 10
#define EH 32
#define NCOLS (EH * D + D + D)   // 4096 (L) + 128 (l2 bias) + 128 (root) = 4352
#define KS 128                   // fp16 single-term: A=hi, B=hi (K=128)
#define BM 128
#define BN 128
#define STAGE_BYTES (BM * 128 + BN * 128)   // 32 KB per stage

// ---------------- scratch (static device globals; no allocation) ----------------
__device__ __half g_Y[N_NODES * NCOLS];    // 142 MB (fp16 Y)
__device__ __half g_A3[N_NODES * KS];
__device__ __half g_B31[NCOLS * KS];
__device__ __half g_B32[NCOLS * KS];
__device__ float g_h1[N_EDGES * EH];
__device__ float g_h2[N_EDGES * EH];
__device__ float g_acc[N_NODES * D];       // zero-init; every combine restores zero
__device__ float g_cnt[N_NODES];
__device__ int   g_idx[2 * N_EDGES];
__device__ int   g_is64;
// edge sort-by-src
__device__ int g_srcCount[N_NODES];
__device__ int g_srcOff[N_NODES];
__device__ int g_rank[N_EDGES];
__device__ int g_perm[N_EDGES];

__device__ __forceinline__ uint32_t smem_u32(const void* p) {
    uint32_t a;
    asm("{ .reg .u64 t; cvta.to.shared.u64 t, %1; cvt.u32.u64 %0, t; }" : "=r"(a) : "l"(p));
    return a;
}
#define CP_ASYNC16(saddr, gptr) \
    asm volatile("cp.async.cg.shared.global [%0], [%1], 16;" :: "r"(saddr), "l"(gptr))
#define CP_COMMIT() asm volatile("cp.async.commit_group;" ::: "memory")
#define CP_WAITG(n) asm volatile("cp.async.wait_group %0;" :: "n"(n) : "memory")

// ---------------- edge_index dtype detection + zero counters ----------------
__global__ void detect_zero(const long long* __restrict__ ei) {
    int i = blockIdx.x * blockDim.x + threadIdx.x;
    if (i < N_NODES) { g_srcCount[i] = 0; g_cnt[i] = 0.f; }
    if (i == 0) {
        int ok = 1;
        for (int k = 0; k < 128; k++) {
            long long v = ei[k];
            if (v < 0 || v >= N_NODES) { ok = 0; break; }
        }
        g_is64 = ok;
    }
}

// ---------------- convert indices + count (fused) ----------------
__global__ void conv_count(const void* __restrict__ ei) {
    int e = blockIdx.x * blockDim.x + threadIdx.x;
    if (e >= N_EDGES) return;
    long long vs, vd;
    if (g_is64) {
        vs = ((const long long*)ei)[e];
        vd = ((const long long*)ei)[N_EDGES + e];
    } else {
        vs = ((const int*)ei)[e];
        vd = ((const int*)ei)[N_EDGES + e];
    }
    int s = (int)vs, d = (int)vd;
    s = s < 0 ? 0 : (s >= N_NODES ? N_NODES - 1 : s);
    d = d < 0 ? 0 : (d >= N_NODES ? N_NODES - 1 : d);
    g_idx[e] = s;
    g_idx[N_EDGES + e] = d;
    g_rank[e] = atomicAdd(&g_srcCount[s], 1);
    atomicAdd(&g_cnt[d], 1.0f);
}

__global__ void scan_counts() {          // 1 block, 1024 threads, 16 elems each
    __shared__ int part[1024];
    int t = threadIdx.x;
    int base = t * 16;
    int local[16];
    int s = 0;
#pragma unroll
    for (int i = 0; i < 16; i++) { local[i] = s; s += g_srcCount[base + i]; }
    part[t] = s;
    __syncthreads();
    for (int off = 1; off < 1024; off <<= 1) {
        int v = (t >= off) ? part[t - off] : 0;
        __syncthreads();
        part[t] += v;
        __syncthreads();
    }
    int pre = (t == 0) ? 0 : part[t - 1];
#pragma unroll
    for (int i = 0; i < 16; i++) g_srcOff[base + i] = pre + local[i];
}

// ---------------- h = relu(edge_attr @ l1w + l1b) both sets + place_edges (fused) ----------------
__global__ void build_h2(const float* __restrict__ ea,
                         const float* __restrict__ wA, const float* __restrict__ bA,
                         const float* __restrict__ wB, const float* __restrict__ bB,
                         float* __restrict__ hA, float* __restrict__ hB) {
    int idx = blockIdx.x * blockDim.x + threadIdx.x;
    if (idx >= N_EDGES * EH) return;
    int e = idx >> 5, j = idx & 31;
    if (j == 0) g_perm[g_srcOff[g_idx[e]] + g_rank[e]] = e;   // place edge in sorted order
    const float* ear = ea + e * EDGE_DIM;
    float sA = bA[j], sB = bB[j];
#pragma unroll
    for (int d = 0; d < EDGE_DIM; d++) {
        float v = ear[d];
        sA = fmaf(v, wA[d * EH + j], sA);
        sB = fmaf(v, wB[d * EH + j], sB);
    }
    hA[idx] = fmaxf(sA, 0.f);
    hB[idx] = fmaxf(sB, 0.f);
}

// ---------------- fp16 conversion of A (layer-1 input only) ----------------
__global__ void convA(const float* __restrict__ X, __half* __restrict__ A3) {
    int idx = blockIdx.x * blockDim.x + threadIdx.x;
    if (idx >= N_NODES * D) return;
    A3[idx] = __float2half_rn(X[idx]);
}

// ---------------- both B' matrices in one kernel ----------------
__global__ void buildB2(const float* __restrict__ l2wA, const float* __restrict__ bA,
                        const float* __restrict__ rootA,
                        const float* __restrict__ l2wB, const float* __restrict__ bB,
                        const float* __restrict__ rootB,
                        __half* __restrict__ B3A, __half* __restrict__ B3B) {
    int idx = blockIdx.x * blockDim.x + threadIdx.x;   // n*128 + k
    if (idx >= NCOLS * D) return;
    int n = idx >> 7, k = idx & 127;
    float vA, vB;
    if (n < EH * D) {
        int pos = (n >> 7) * (D * D) + k * D + (n & 127);
        vA = l2wA[pos]; vB = l2wB[pos];
    } else if (n < EH * D + D) {
        int pos = k * D + (n - EH * D);
        vA = bA[pos]; vB = bB[pos];
    } else {
        int pos = k * D + (n - EH * D - D);
        vA = rootA[pos]; vB = rootB[pos];
    }
    B3A[idx] = __float2half_rn(vA);
    B3B[idx] = __float2half_rn(vB);
}

// ---------------- HMMA GEMM: K=128 (2 chunks, both prefetched), CTA 128x128, warp 64x32 ----------------
__global__ void __launch_bounds__(256) gemm_mma(const __half* __restrict__ A,
                                                const __half* __restrict__ B,
                                                __half* __restrict__ C) {
    extern __shared__ __align__(1024) char smem[];
    const int tid = threadIdx.x, lane = tid & 31, wid = tid >> 5;
    const int warp_m = wid & 1, warp_n = wid >> 1;       // 2 x 4
    const int rowBase = blockIdx.y * BM;
    const int colBase = blockIdx.x * BN;
    const uint32_t smemU = smem_u32(smem);
    const char* Ab = (const char*)A;
    const char* Bb = (const char*)B;

    float acc[4][4][4];
#pragma unroll
    for (int i = 0; i < 4; i++)
#pragma unroll
        for (int j = 0; j < 4; j++)
#pragma unroll
            for (int r = 0; r < 4; r++) acc[i][j][r] = 0.f;

    const int ldr = tid >> 3;
    const int ldc = tid & 7;

    auto load_stage = [&](int st, int ch) {
        uint32_t sa = smemU + st * STAGE_BYTES;
        uint32_t sb = sa + BM * 128;
#pragma unroll
        for (int i = 0; i < 4; i++) {
            int r = ldr + i * 32;
            uint32_t soff = (uint32_t)(r * 128 + ((ldc * 16) ^ ((r & 7) * 16)));
            CP_ASYNC16(sa + soff, Ab + (size_t)(rowBase + r) * (KS * 2) + ch * 128 + ldc * 16);
            CP_ASYNC16(sb + soff, Bb + (size_t)(colBase + r) * (KS * 2) + ch * 128 + ldc * 16);
        }
        CP_COMMIT();
    };

    load_stage(0, 0);
    load_stage(1, 1);

#pragma unroll
    for (int ch = 0; ch < 2; ch++) {               // K = 128 = 2 chunks of 64
        if (ch == 0) { CP_WAITG(1); } else { CP_WAITG(0); }
        __syncthreads();

        const uint32_t aB = smemU + ch * STAGE_BYTES;
        const uint32_t bB = aB + BM * 128;
#pragma unroll
        for (int s = 0; s < 4; s++) {
            uint32_t af[4][4], bf[4][2];
#pragma unroll
            for (int i = 0; i < 4; i++) {
                int row = warp_m * 64 + i * 16 + (lane & 15);
                int kb = s * 32 + ((lane >> 4) << 4);
                uint32_t addr = aB + row * 128 + (kb ^ ((row & 7) * 16));
                asm volatile("ldmatrix.sync.aligned.m8n8.x4.shared.b16 {%0,%1,%2,%3}, [%4];"
                             : "=r"(af[i][0]), "=r"(af[i][1]), "=r"(af[i][2]), "=r"(af[i][3])
                             : "r"(addr));
            }
            // B fragments: one x4 ldmatrix covers two adjacent n8 tiles (j, j+1)
#pragma unroll
            for (int jp = 0; jp < 2; jp++) {
                int nrow = warp_n * 32 + (jp * 2 + (lane >> 4)) * 8 + (lane & 7);
                int kb = s * 32 + (((lane >> 3) & 1) << 4);
                uint32_t addr = bB + nrow * 128 + (kb ^ ((nrow & 7) * 16));
                asm volatile("ldmatrix.sync.aligned.m8n8.x4.shared.b16 {%0,%1,%2,%3}, [%4];"
                             : "=r"(bf[jp * 2][0]), "=r"(bf[jp * 2][1]),
                               "=r"(bf[jp * 2 + 1][0]), "=r"(bf[jp * 2 + 1][1])
                             : "r"(addr));
            }
#pragma unroll
            for (int i = 0; i < 4; i++)
#pragma unroll
                for (int j = 0; j < 4; j++)
                    asm volatile(
                        "mma.sync.aligned.m16n8k16.row.col.f32.f16.f16.f32 "
                        "{%0,%1,%2,%3}, {%4,%5,%6,%7}, {%8,%9}, {%0,%1,%2,%3};"
                        : "+f"(acc[i][j][0]), "+f"(acc[i][j][1]),
                          "+f"(acc[i][j][2]), "+f"(acc[i][j][3])
                        : "r"(af[i][0]), "r"(af[i][1]), "r"(af[i][2]), "r"(af[i][3]),
                          "r"(bf[j][0]), "r"(bf[j][1]));
        }
        if (ch == 0) __syncthreads();
    }

    // Epilogue: fp16 stores (half2)
#pragma unroll
    for (int i = 0; i < 4; i++) {
        int r0 = rowBase + warp_m * 64 + i * 16 + (lane >> 2);
#pragma unroll
        for (int j = 0; j < 4; j++) {
            int col = colBase + warp_n * 32 + j * 8 + (lane & 3) * 2;
            *(__half2*)&C[(size_t)r0 * NCOLS + col] =
                __floats2half2_rn(acc[i][j][0], acc[i][j][1]);
            *(__half2*)&C[(size_t)(r0 + 8) * NCOLS + col] =
                __floats2half2_rn(acc[i][j][2], acc[i][j][3]);
        }
    }
}

// ---------------- edge message (src-sorted flat, fp16 gather) + scatter-add ----------------
__global__ void __launch_bounds__(256) edge_msg(const float* __restrict__ h,
                                                const __half* __restrict__ Y) {
    const int q = threadIdx.x >> 6;           // edge-within-block 0..3
    const int slot = blockIdx.x * 4 + q;
    const int o2 = threadIdx.x & 63;          // half2 column index
    __shared__ float sh[4][EH];
    __shared__ int se[4];
    if (o2 == 0) se[q] = g_perm[slot];
    __syncthreads();
    const int eo = se[q];
    if (o2 < EH) sh[q][o2] = h[eo * EH + o2];
    __syncthreads();
    const int src = g_idx[eo];
    const int dst = g_idx[N_EDGES + eo];
    const __half2* y2 = (const __half2*)(Y + (size_t)src * NCOLS);
    float2 b2 = __half22float2(y2[(EH * D) / 2 + o2]);    // l2-bias columns
    float mx = b2.x, my = b2.y;
#pragma unroll
    for (int k = 0; k < EH; k++) {
        float2 v = __half22float2(y2[k * 64 + o2]);
        float hk = sh[q][k];
        mx = fmaf(hk, v.x, mx);
        my = fmaf(hk, v.y, my);
    }
    atomicAdd(&g_acc[dst * D + 2 * o2], mx);
    atomicAdd(&g_acc[dst * D + 2 * o2 + 1], my);
}

// ---------------- combine: out = Yroot + acc/max(cnt,1) + bias; resets acc to 0 ----------------
__global__ void combine(const __half* __restrict__ Y, const float* __restrict__ bias,
                        float* __restrict__ outf, __half* __restrict__ A3,
                        int do_relu) {
    int idx = blockIdx.x * blockDim.x + threadIdx.x;
    if (idx >= N_NODES * D) return;
    int n = idx >> 7, o = idx & 127;
    float v = __half2float(Y[(size_t)n * NCOLS + EH * D + D + o])
            + g_acc[idx] / fmaxf(g_cnt[n], 1.f) + bias[o];
    g_acc[idx] = 0.f;                         // reset for next layer / next replay
    if (do_relu) v = fmaxf(v, 0.f);
    if (outf) outf[idx] = v;
    if (A3) A3[idx] = __float2half_rn(v);
}

// ---------------- launcher ----------------
extern "C" void kernel_launch(void* const* d_in, const int* in_sizes, int n_in,
                              void* d_out, int out_size) {
    const float* x       = (const float*)d_in[0];
    const void*  ei      = d_in[1];
    const float* ea      = (const float*)d_in[2];
    const float* w1_l1   = (const float*)d_in[3];
    const float* b1_l1   = (const float*)d_in[4];
    const float* w1_l2   = (const float*)d_in[5];
    const float* b1_l2   = (const float*)d_in[6];
    const float* w1_root = (const float*)d_in[7];
    const float* b1      = (const float*)d_in[8];
    const float* w2_l1   = (const float*)d_in[9];
    const float* b2_l1   = (const float*)d_in[10];
    const float* w2_l2   = (const float*)d_in[11];
    const float* b2_l2   = (const float*)d_in[12];
    const float* w2_root = (const float*)d_in[13];
    const float* b2      = (const float*)d_in[14];
    float*       out     = (float*)d_out;

    __half *Y, *A3, *B31, *B32;
    float *h1, *h2;
    cudaGetSymbolAddress((void**)&Y,   g_Y);
    cudaGetSymbolAddress((void**)&A3,  g_A3);
    cudaGetSymbolAddress((void**)&B31, g_B31);
    cudaGetSymbolAddress((void**)&B32, g_B32);
    cudaGetSymbolAddress((void**)&h1,  g_h1);
    cudaGetSymbolAddress((void**)&h2,  g_h2);

    const int SMEM_GEMM = 2 * STAGE_BYTES;              // 64 KB
    cudaFuncSetAttribute(gemm_mma, cudaFuncAttributeMaxDynamicSharedMemorySize, SMEM_GEMM);

    // ---- setup (indices+counts, scan, sort+edge MLP, weights) ----
    detect_zero<<<(N_NODES + 255) / 256, 256>>>((const long long*)ei);
    conv_count<<<(N_EDGES + 255) / 256, 256>>>(ei);
    scan_counts<<<1, 1024>>>();
    build_h2<<<(N_EDGES * EH + 255) / 256, 256>>>(ea, w1_l1, b1_l1, w2_l1, b2_l1, h1, h2);
    buildB2<<<(NCOLS * D + 255) / 256, 256>>>(w1_l2, b1_l2, w1_root,
                                              w2_l2, b2_l2, w2_root, B31, B32);

    dim3 gGemm(NCOLS / BN, N_NODES / BM);               // (34, 128)
    const int zgrid = (N_NODES * D + 255) / 256;
    const int egrid = N_EDGES / 4;

    // ---- layer 1 ----
    convA<<<zgrid, 256>>>(x, A3);
    gemm_mma<<<gGemm, 256, SMEM_GEMM>>>(A3, B31, Y);
    edge_msg<<<egrid, 256>>>(h1, Y);
    combine<<<zgrid, 256>>>(Y, b1, nullptr, A3, 1);
    // ---- layer 2 ----
    gemm_mma<<<gGemm, 256, SMEM_GEMM>>>(A3, B32, Y);
    edge_msg<<<egrid, 256>>>(h2, Y);
    combine<<<zgrid, 256>>>(Y, b2, nullptr, A3, 1);
    // ---- layer 3 ----
    gemm_mma<<<gGemm, 256, SMEM_GEMM>>>(A3, B32, Y);
    edge_msg<<<egrid, 256>>>(h2, Y);
    combine<<<zgrid, 256>>>(Y, b2, out, nullptr, 0);
}

// round 13
// speedup vs baseline: 1.5412x; 1.0480x over previous
#include <cuda_runtime.h>
#include <cuda_fp16.h>
#include <cstdint>

#define N_NODES 16384
#define N_EDGES 32768
#define D 128
#define EDGE_DIM 10
#define EH 32
#define NCOLS (EH * D + D + D)   // 4096 (L) + 128 (l2 bias) + 128 (root) = 4352
#define KS 128                   // fp16 single-term: A=hi, B=hi (K=128)
#define BM 128
#define BN 128
#define STAGE_BYTES (BM * 128 + BN * 128)   // 32 KB per stage

// ---------------- scratch (static device globals; no allocation) ----------------
__device__ __half g_Y[N_NODES * NCOLS];    // 142 MB (fp16 Y)
__device__ __half g_A3[N_NODES * KS];
__device__ __half g_B31[NCOLS * KS];
__device__ __half g_B32[NCOLS * KS];
__device__ float g_h1[N_EDGES * EH];
__device__ float g_h2[N_EDGES * EH];
__device__ float g_acc[N_NODES * D];       // zero-init; every combine restores zero
__device__ float g_cnt[N_NODES];
__device__ int   g_idx[2 * N_EDGES];
__device__ int   g_is64;
// edge sort-by-src
__device__ int g_srcCount[N_NODES];
__device__ int g_srcOff[N_NODES];
__device__ int g_rank[N_EDGES];
__device__ int g_perm[N_EDGES];

__device__ __forceinline__ uint32_t smem_u32(const void* p) {
    uint32_t a;
    asm("{ .reg .u64 t; cvta.to.shared.u64 t, %1; cvt.u32.u64 %0, t; }" : "=r"(a) : "l"(p));
    return a;
}
#define CP_ASYNC16(saddr, gptr) \
    asm volatile("cp.async.cg.shared.global [%0], [%1], 16;" :: "r"(saddr), "l"(gptr))
#define CP_COMMIT() asm volatile("cp.async.commit_group;" ::: "memory")
#define CP_WAITG(n) asm volatile("cp.async.wait_group %0;" :: "n"(n) : "memory")

// ---------------- edge_index dtype detection + zero counters ----------------
__global__ void detect_zero(const long long* __restrict__ ei) {
    int i = blockIdx.x * blockDim.x + threadIdx.x;
    if (i < N_NODES) { g_srcCount[i] = 0; g_cnt[i] = 0.f; }
    if (i == 0) {
        int ok = 1;
        for (int k = 0; k < 128; k++) {
            long long v = ei[k];
            if (v < 0 || v >= N_NODES) { ok = 0; break; }
        }
        g_is64 = ok;
    }
}

// ---------------- convert indices + count (fused) ----------------
__global__ void conv_count(const void* __restrict__ ei) {
    int e = blockIdx.x * blockDim.x + threadIdx.x;
    if (e >= N_EDGES) return;
    long long vs, vd;
    if (g_is64) {
        vs = ((const long long*)ei)[e];
        vd = ((const long long*)ei)[N_EDGES + e];
    } else {
        vs = ((const int*)ei)[e];
        vd = ((const int*)ei)[N_EDGES + e];
    }
    int s = (int)vs, d = (int)vd;
    s = s < 0 ? 0 : (s >= N_NODES ? N_NODES - 1 : s);
    d = d < 0 ? 0 : (d >= N_NODES ? N_NODES - 1 : d);
    g_idx[e] = s;
    g_idx[N_EDGES + e] = d;
    g_rank[e] = atomicAdd(&g_srcCount[s], 1);
    atomicAdd(&g_cnt[d], 1.0f);
}

__global__ void scan_counts() {          // 1 block, 1024 threads, 16 elems each
    __shared__ int part[1024];
    int t = threadIdx.x;
    int base = t * 16;
    int local[16];
    int s = 0;
#pragma unroll
    for (int i = 0; i < 16; i++) { local[i] = s; s += g_srcCount[base + i]; }
    part[t] = s;
    __syncthreads();
    for (int off = 1; off < 1024; off <<= 1) {
        int v = (t >= off) ? part[t - off] : 0;
        __syncthreads();
        part[t] += v;
        __syncthreads();
    }
    int pre = (t == 0) ? 0 : part[t - 1];
#pragma unroll
    for (int i = 0; i < 16; i++) g_srcOff[base + i] = pre + local[i];
}

// ---------------- h = relu(edge_attr @ l1w + l1b) both sets + place_edges (fused) ----------------
__global__ void build_h2(const float* __restrict__ ea,
                         const float* __restrict__ wA, const float* __restrict__ bA,
                         const float* __restrict__ wB, const float* __restrict__ bB,
                         float* __restrict__ hA, float* __restrict__ hB) {
    int idx = blockIdx.x * blockDim.x + threadIdx.x;
    if (idx >= N_EDGES * EH) return;
    int e = idx >> 5, j = idx & 31;
    if (j == 0) g_perm[g_srcOff[g_idx[e]] + g_rank[e]] = e;   // place edge in sorted order
    const float* ear = ea + e * EDGE_DIM;
    float sA = bA[j], sB = bB[j];
#pragma unroll
    for (int d = 0; d < EDGE_DIM; d++) {
        float v = ear[d];
        sA = fmaf(v, wA[d * EH + j], sA);
        sB = fmaf(v, wB[d * EH + j], sB);
    }
    hA[idx] = fmaxf(sA, 0.f);
    hB[idx] = fmaxf(sB, 0.f);
}

// ---------------- fp16 conversion of A (layer-1 input only) ----------------
__global__ void convA(const float* __restrict__ X, __half* __restrict__ A3) {
    int idx = blockIdx.x * blockDim.x + threadIdx.x;
    if (idx >= N_NODES * D) return;
    A3[idx] = __float2half_rn(X[idx]);
}

// ---------------- both B' matrices in one kernel ----------------
__global__ void buildB2(const float* __restrict__ l2wA, const float* __restrict__ bA,
                        const float* __restrict__ rootA,
                        const float* __restrict__ l2wB, const float* __restrict__ bB,
                        const float* __restrict__ rootB,
                        __half* __restrict__ B3A, __half* __restrict__ B3B) {
    int idx = blockIdx.x * blockDim.x + threadIdx.x;   // n*128 + k
    if (idx >= NCOLS * D) return;
    int n = idx >> 7, k = idx & 127;
    float vA, vB;
    if (n < EH * D) {
        int pos = (n >> 7) * (D * D) + k * D + (n & 127);
        vA = l2wA[pos]; vB = l2wB[pos];
    } else if (n < EH * D + D) {
        int pos = k * D + (n - EH * D);
        vA = bA[pos]; vB = bB[pos];
    } else {
        int pos = k * D + (n - EH * D - D);
        vA = rootA[pos]; vB = rootB[pos];
    }
    B3A[idx] = __float2half_rn(vA);
    B3B[idx] = __float2half_rn(vB);
}

// ---------------- HMMA GEMM: K=128 fully prefetched, CTA 128x128, 4 warps of 64x64 ----------------
__global__ void __launch_bounds__(128) gemm_mma(const __half* __restrict__ A,
                                                const __half* __restrict__ B,
                                                __half* __restrict__ C) {
    extern __shared__ __align__(1024) char smem[];
    const int tid = threadIdx.x, lane = tid & 31, wid = tid >> 5;
    const int warp_m = wid & 1, warp_n = wid >> 1;       // 2 x 2, each 64x64
    const int rowBase = blockIdx.y * BM;
    const int colBase = blockIdx.x * BN;
    const uint32_t smemU = smem_u32(smem);
    const char* Ab = (const char*)A;
    const char* Bb = (const char*)B;

    float acc[4][8][4];
#pragma unroll
    for (int i = 0; i < 4; i++)
#pragma unroll
        for (int j = 0; j < 8; j++)
#pragma unroll
            for (int r = 0; r < 4; r++) acc[i][j][r] = 0.f;

    const int ldr = tid >> 3;            // 0..15
    const int ldc = tid & 7;             // 16B unit within 128B row

    auto load_stage = [&](int st, int ch) {
        uint32_t sa = smemU + st * STAGE_BYTES;
        uint32_t sb = sa + BM * 128;
#pragma unroll
        for (int i = 0; i < 8; i++) {
            int r = ldr + i * 16;
            uint32_t soff = (uint32_t)(r * 128 + ((ldc * 16) ^ ((r & 7) * 16)));
            CP_ASYNC16(sa + soff, Ab + (size_t)(rowBase + r) * (KS * 2) + ch * 128 + ldc * 16);
            CP_ASYNC16(sb + soff, Bb + (size_t)(colBase + r) * (KS * 2) + ch * 128 + ldc * 16);
        }
        CP_COMMIT();
    };

    load_stage(0, 0);
    load_stage(1, 1);

#pragma unroll
    for (int ch = 0; ch < 2; ch++) {               // K = 128 = 2 chunks of 64
        if (ch == 0) { CP_WAITG(1); } else { CP_WAITG(0); }
        __syncthreads();

        const uint32_t aB = smemU + ch * STAGE_BYTES;
        const uint32_t bB = aB + BM * 128;
#pragma unroll
        for (int s = 0; s < 4; s++) {
            uint32_t af[4][4], bf[8][2];
#pragma unroll
            for (int i = 0; i < 4; i++) {
                int row = warp_m * 64 + i * 16 + (lane & 15);
                int kb = s * 32 + ((lane >> 4) << 4);
                uint32_t addr = aB + row * 128 + (kb ^ ((row & 7) * 16));
                asm volatile("ldmatrix.sync.aligned.m8n8.x4.shared.b16 {%0,%1,%2,%3}, [%4];"
                             : "=r"(af[i][0]), "=r"(af[i][1]), "=r"(af[i][2]), "=r"(af[i][3])
                             : "r"(addr));
            }
            // B fragments: one x4 ldmatrix covers two adjacent n8 tiles
#pragma unroll
            for (int jp = 0; jp < 4; jp++) {
                int nrow = warp_n * 64 + (jp * 2 + (lane >> 4)) * 8 + (lane & 7);
                int kb = s * 32 + (((lane >> 3) & 1) << 4);
                uint32_t addr = bB + nrow * 128 + (kb ^ ((nrow & 7) * 16));
                asm volatile("ldmatrix.sync.aligned.m8n8.x4.shared.b16 {%0,%1,%2,%3}, [%4];"
                             : "=r"(bf[jp * 2][0]), "=r"(bf[jp * 2][1]),
                               "=r"(bf[jp * 2 + 1][0]), "=r"(bf[jp * 2 + 1][1])
                             : "r"(addr));
            }
#pragma unroll
            for (int i = 0; i < 4; i++)
#pragma unroll
                for (int j = 0; j < 8; j++)
                    asm volatile(
                        "mma.sync.aligned.m16n8k16.row.col.f32.f16.f16.f32 "
                        "{%0,%1,%2,%3}, {%4,%5,%6,%7}, {%8,%9}, {%0,%1,%2,%3};"
                        : "+f"(acc[i][j][0]), "+f"(acc[i][j][1]),
                          "+f"(acc[i][j][2]), "+f"(acc[i][j][3])
                        : "r"(af[i][0]), "r"(af[i][1]), "r"(af[i][2]), "r"(af[i][3]),
                          "r"(bf[j][0]), "r"(bf[j][1]));
        }
        if (ch == 0) __syncthreads();
    }

    // Epilogue: fp16 stores (half2), warp region 64x64
#pragma unroll
    for (int i = 0; i < 4; i++) {
        int r0 = rowBase + warp_m * 64 + i * 16 + (lane >> 2);
#pragma unroll
        for (int j = 0; j < 8; j++) {
            int col = colBase + warp_n * 64 + j * 8 + (lane & 3) * 2;
            *(__half2*)&C[(size_t)r0 * NCOLS + col] =
                __floats2half2_rn(acc[i][j][0], acc[i][j][1]);
            *(__half2*)&C[(size_t)(r0 + 8) * NCOLS + col] =
                __floats2half2_rn(acc[i][j][2], acc[i][j][3]);
        }
    }
}

// ---------------- edge message (src-sorted flat, fp16 gather) + scatter-add ----------------
__global__ void __launch_bounds__(256) edge_msg(const float* __restrict__ h,
                                                const __half* __restrict__ Y) {
    const int q = threadIdx.x >> 6;           // edge-within-block 0..3
    const int slot = blockIdx.x * 4 + q;
    const int o2 = threadIdx.x & 63;          // half2 column index
    __shared__ float sh[4][EH];
    __shared__ int se[4];
    if (o2 == 0) se[q] = g_perm[slot];
    __syncthreads();
    const int eo = se[q];
    if (o2 < EH) sh[q][o2] = h[eo * EH + o2];
    __syncthreads();
    const int src = g_idx[eo];
    const int dst = g_idx[N_EDGES + eo];
    const __half2* y2 = (const __half2*)(Y + (size_t)src * NCOLS);
    float2 b2 = __half22float2(y2[(EH * D) / 2 + o2]);    // l2-bias columns
    float mx = b2.x, my = b2.y;
#pragma unroll
    for (int k = 0; k < EH; k++) {
        float2 v = __half22float2(y2[k * 64 + o2]);
        float hk = sh[q][k];
        mx = fmaf(hk, v.x, mx);
        my = fmaf(hk, v.y, my);
    }
    atomicAdd(&g_acc[dst * D + 2 * o2], mx);
    atomicAdd(&g_acc[dst * D + 2 * o2 + 1], my);
}

// ---------------- combine: out = Yroot + acc/max(cnt,1) + bias; resets acc to 0 ----------------
__global__ void combine(const __half* __restrict__ Y, const float* __restrict__ bias,
                        float* __restrict__ outf, __half* __restrict__ A3,
                        int do_relu) {
    int idx = blockIdx.x * blockDim.x + threadIdx.x;
    if (idx >= N_NODES * D) return;
    int n = idx >> 7, o = idx & 127;
    float v = __half2float(Y[(size_t)n * NCOLS + EH * D + D + o])
            + g_acc[idx] / fmaxf(g_cnt[n], 1.f) + bias[o];
    g_acc[idx] = 0.f;                         // reset for next layer / next replay
    if (do_relu) v = fmaxf(v, 0.f);
    if (outf) outf[idx] = v;
    if (A3) A3[idx] = __float2half_rn(v);
}

// ---------------- launcher ----------------
extern "C" void kernel_launch(void* const* d_in, const int* in_sizes, int n_in,
                              void* d_out, int out_size) {
    const float* x       = (const float*)d_in[0];
    const void*  ei      = d_in[1];
    const float* ea      = (const float*)d_in[2];
    const float* w1_l1   = (const float*)d_in[3];
    const float* b1_l1   = (const float*)d_in[4];
    const float* w1_l2   = (const float*)d_in[5];
    const float* b1_l2   = (const float*)d_in[6];
    const float* w1_root = (const float*)d_in[7];
    const float* b1      = (const float*)d_in[8];
    const float* w2_l1   = (const float*)d_in[9];
    const float* b2_l1   = (const float*)d_in[10];
    const float* w2_l2   = (const float*)d_in[11];
    const float* b2_l2   = (const float*)d_in[12];
    const float* w2_root = (const float*)d_in[13];
    const float* b2      = (const float*)d_in[14];
    float*       out     = (float*)d_out;

    __half *Y, *A3, *B31, *B32;
    float *h1, *h2;
    cudaGetSymbolAddress((void**)&Y,   g_Y);
    cudaGetSymbolAddress((void**)&A3,  g_A3);
    cudaGetSymbolAddress((void**)&B31, g_B31);
    cudaGetSymbolAddress((void**)&B32, g_B32);
    cudaGetSymbolAddress((void**)&h1,  g_h1);
    cudaGetSymbolAddress((void**)&h2,  g_h2);

    const int SMEM_GEMM = 2 * STAGE_BYTES;              // 64 KB
    cudaFuncSetAttribute(gemm_mma, cudaFuncAttributeMaxDynamicSharedMemorySize, SMEM_GEMM);

    // ---- setup (indices+counts, scan, sort+edge MLP, weights) ----
    detect_zero<<<(N_NODES + 255) / 256, 256>>>((const long long*)ei);
    conv_count<<<(N_EDGES + 255) / 256, 256>>>(ei);
    scan_counts<<<1, 1024>>>();
    build_h2<<<(N_EDGES * EH + 255) / 256, 256>>>(ea, w1_l1, b1_l1, w2_l1, b2_l1, h1, h2);
    buildB2<<<(NCOLS * D + 255) / 256, 256>>>(w1_l2, b1_l2, w1_root,
                                              w2_l2, b2_l2, w2_root, B31, B32);

    dim3 gGemm(NCOLS / BN, N_NODES / BM);               // (34, 128)
    const int zgrid = (N_NODES * D + 255) / 256;
    const int egrid = N_EDGES / 4;

    // ---- layer 1 ----
    convA<<<zgrid, 256>>>(x, A3);
    gemm_mma<<<gGemm, 128, SMEM_GEMM>>>(A3, B31, Y);
    edge_msg<<<egrid, 256>>>(h1, Y);
    combine<<<zgrid, 256>>>(Y, b1, nullptr, A3, 1);
    // ---- layer 2 ----
    gemm_mma<<<gGemm, 128, SMEM_GEMM>>>(A3, B32, Y);
    edge_msg<<<egrid, 256>>>(h2, Y);
    combine<<<zgrid, 256>>>(Y, b2, nullptr, A3, 1);
    // ---- layer 3 ----
    gemm_mma<<<gGemm, 128, SMEM_GEMM>>>(A3, B32, Y);
    edge_msg<<<egrid, 256>>>(h2, Y);
    combine<<<zgrid, 256>>>(Y, b2, out, nullptr, 0);
}